// round 9
// baseline (speedup 1.0000x reference)
#include <cuda_runtime.h>
#include <cuda_fp16.h>

// out[r,:] = FWHT_8192(scatter(u[r,:], idx)) / sqrt(8192)
//
// Persistent-CTA version: grid = 888 (6 CTAs/SM x 148 SMs), each CTA pulls rows
// from a global atomic queue. Next row's u (4KB) is prefetched via cp.async into
// a smem stage while the current row runs phases A-C, so the DRAM read stream
// overlaps compute instead of idling.
//
// Phase layout (identical math to the validated R6 kernel):
//   A: bits 4:0  packed f32x2 (bit0 pair)       B: bits 8:5 (bit4 passenger)
//   C: bits 12:9 (bit8 passenger)
// All smem traffic fp16 (half2); arithmetic f32. 1/sqrt(8192) folded into the
// input conversion.

#define D_DIM 8192
#define K_DIM 1024
#define NT    256
#define NCTA  888            // 6 * 148
#define SCALE_F 0.0110485434560398047f  // 1/sqrt(8192)

__device__ unsigned g_ctr;

__global__ void reset_ctr_kernel() { g_ctr = NCTA; }

__device__ __forceinline__ float2 fadd2(float2 a, float2 b) {
    float2 c;
    asm("add.rn.f32x2 %0, %1, %2;"
        : "=l"(reinterpret_cast<unsigned long long &>(c))
        : "l"(reinterpret_cast<const unsigned long long &>(a)),
          "l"(reinterpret_cast<const unsigned long long &>(b)));
    return c;
}
__device__ __forceinline__ float2 ffma2(float2 a, float2 b, float2 c) {
    float2 d;
    asm("fma.rn.f32x2 %0, %1, %2, %3;"
        : "=l"(reinterpret_cast<unsigned long long &>(d))
        : "l"(reinterpret_cast<const unsigned long long &>(a)),
          "l"(reinterpret_cast<const unsigned long long &>(b)),
          "l"(reinterpret_cast<const unsigned long long &>(c)));
    return d;
}

__global__ __launch_bounds__(NT, 6)
void fwht_up_kernel(const float* __restrict__ u,
                    const int*   __restrict__ idx,
                    float*       __restrict__ out)
{
    __shared__ __align__(16) __half2 zb[4096];   // scatter buffer (fp16)
    __shared__ __align__(16) __half2 tb[4096];   // transpose buffer (fp16)
    __shared__ __align__(16) float   stage[K_DIM]; // u prefetch stage (4KB)
    __shared__ int s_next;

    const int t = threadIdx.x;    // 8 bits

    // ---- loop-invariant scatter mapping (cell<<1 | component) ----
    int cell2[4];
    {
        const int4 iv = reinterpret_cast<const int4*>(idx)[t];
        int vs[4] = {iv.x, iv.y, iv.z, iv.w};
#pragma unroll
        for (int j = 0; j < 4; j++) {
            int v  = vs[j];
            int tv = v >> 5;
            int cell = tv * 16 + (((v >> 1) & 15) ^ ((tv >> 1) & 15));
            cell2[j] = (cell << 1) | (v & 1);
        }
    }

    // ---- loop-invariant addresses ----
    const int s1   = (t >> 1) & 15;
    const int A2   = ((t >> 5) << 9) | ((t & 15) << 5) | (((t >> 4) & 1) << 4);
    const int A3   = ((t >> 5) << 9) | (((t >> 4) & 1) << 4);
    const int B2c  = ((t >> 4) << 8) | (t & 15);
    const int selw = (t >> 4) & 1;
    const int B3c  = ((t >> 5) << 5) | (t & 15);
    const float2 NEG1 = make_float2(-1.f, -1.f);
    const unsigned stage_sa =
        (unsigned)__cvta_generic_to_shared(stage) + (unsigned)(t * 16);

    int row = blockIdx.x;

    // ---- prologue: prefetch u[row], zero zb fully ----
    {
        const float* g = u + (size_t)row * K_DIM + t * 4;
        asm volatile("cp.async.cg.shared.global [%0], [%1], 16;\n"
                     "cp.async.commit_group;\n" :: "r"(stage_sa), "l"(g) : "memory");
    }
    {
        float4* z4 = reinterpret_cast<float4*>(zb);
#pragma unroll
        for (int q = 0; q < 4; q++)
            z4[t + q * NT] = make_float4(0.f, 0.f, 0.f, 0.f);
    }

    while (row < D_DIM) {   // D_DIM == number of rows (8192)
        if (t == 0) s_next = (int)atomicAdd(&g_ctr, 1u);
        asm volatile("cp.async.wait_group 0;" ::: "memory");
        __syncthreads();                       // B1: stage ready, zb zeroed, s_next visible
        const int next = s_next;

        // ---- scatter: read staged u, scale, fp16 atomics into zb ----
        {
            const float4 u4 = reinterpret_cast<const float4*>(stage)[t];
            const float uv[4] = {u4.x, u4.y, u4.z, u4.w};
#pragma unroll
            for (int j = 0; j < 4; j++) {
                int c2 = cell2[j];
                unsigned hs = (unsigned)__half_as_ushort(
                                  __float2half_rn(uv[j] * SCALE_F));
                unsigned packed = hs << ((c2 & 1) << 4);
                atomicAdd(&zb[c2 >> 1], *reinterpret_cast<__half2*>(&packed));
            }
        }
        __syncthreads();                       // B2: zb complete, stage consumed

        // ---- prefetch next row's u into the (now free) stage ----
        if (next < D_DIM) {
            const float* g = u + (size_t)next * K_DIM + t * 4;
            asm volatile("cp.async.cg.shared.global [%0], [%1], 16;\n"
                         "cp.async.commit_group;\n" :: "r"(stage_sa), "l"(g) : "memory");
        }

        float2 x[16];

        // ---- R1: thread owns bits 12:5 = t; pair over bit0 at bits4:1 = q ----
#pragma unroll
        for (int q = 0; q < 16; q++)
            x[q] = __half22float2(zb[t * 16 + (q ^ s1)]);

        // zero own cells for the next row (thread-private; no barrier needed)
        {
            float4* own = reinterpret_cast<float4*>(zb + t * 16);
#pragma unroll
            for (int q = 0; q < 4; q++)
                own[q] = make_float4(0.f, 0.f, 0.f, 0.f);
        }

        // ---- phase A: bits 4:1 packed, then bit0 scalar ----
#pragma unroll
        for (int s = 1; s < 16; s <<= 1)
#pragma unroll
            for (int i = 0; i < 16; i++)
                if ((i & s) == 0) {
                    float2 a = x[i], b = x[i + s];
                    x[i]     = fadd2(a, b);
                    x[i + s] = ffma2(b, NEG1, a);
                }
#pragma unroll
        for (int i = 0; i < 16; i++) {
            float a = x[i].x, b = x[i].y;
            x[i].x = a + b;  x[i].y = a - b;
        }

        // ---- W2: pack half2 along bit4 ----
#pragma unroll
        for (int m = 0; m < 16; m++) {
            float f0 = (m & 1) ? x[m >> 1].y       : x[m >> 1].x;
            float f1 = (m & 1) ? x[(m >> 1) + 8].y : x[(m >> 1) + 8].x;
            tb[A2 | ((t & 15) ^ m)] = __floats2half2_rn(f0, f1);
        }
        __syncthreads();                       // B3

        // ---- R2: pair over bit4 at bits8:5 = j ----
#pragma unroll
        for (int j = 0; j < 16; j++)
            x[j] = __half22float2(tb[A3 | (j << 5) | (j ^ (t & 15))]);

        // ---- phase B: bits 8:5 packed (bit4 passenger) ----
#pragma unroll
        for (int s = 1; s < 16; s <<= 1)
#pragma unroll
            for (int i = 0; i < 16; i++)
                if ((i & s) == 0) {
                    float2 a = x[i], b = x[i + s];
                    x[i]     = fadd2(a, b);
                    x[i + s] = ffma2(b, NEG1, a);
                }
        __syncthreads();                       // B4: all R2 reads done

        // ---- W3: pack half2 along bit8 ----
#pragma unroll
        for (int i2 = 0; i2 < 16; i2++) {
            int jl = i2 >> 1, c = i2 & 1;
            float f0 = c ? x[jl].y     : x[jl].x;
            float f1 = c ? x[jl + 8].y : x[jl + 8].x;
            tb[B2c | (jl << 5) | ((c ^ selw) << 4)] = __floats2half2_rn(f0, f1);
        }
        __syncthreads();                       // B5

        // ---- R3: pair over bit8 at bits12:9 = g ----
#pragma unroll
        for (int g = 0; g < 16; g++)
            x[g] = __half22float2(tb[(g << 8) | B3c | ((selw ^ (g & 1)) << 4)]);

        // ---- phase C: bits 12:9 packed (bit8 passenger) ----
#pragma unroll
        for (int s = 1; s < 16; s <<= 1)
#pragma unroll
            for (int i = 0; i < 16; i++)
                if ((i & s) == 0) {
                    float2 a = x[i], b = x[i + s];
                    x[i]     = fadd2(a, b);
                    x[i + s] = ffma2(b, NEG1, a);
                }

        // ---- coalesced stores (scale already folded at input) ----
        float* orow = out + (size_t)row * D_DIM;
#pragma unroll
        for (int g = 0; g < 16; g++) {
            orow[(g << 9) | t]       = x[g].x;
            orow[(g << 9) | 256 | t] = x[g].y;
        }

        row = next;
    }
}

extern "C" void kernel_launch(void* const* d_in, const int* in_sizes, int n_in,
                              void* d_out, int out_size)
{
    const float* u   = (const float*)d_in[0];
    const int*   idx = (const int*)d_in[1];
    float*       out = (float*)d_out;

    reset_ctr_kernel<<<1, 1>>>();
    fwht_up_kernel<<<NCTA, NT>>>(u, idx, out);
}